// round 3
// baseline (speedup 1.0000x reference)
#include <cuda_runtime.h>
#include <cuda_bf16.h>

#define N_NODES  50000
#define N_EDGES  1600000
#define IN_FEATS 128
#define HID      64

// ---------------- device scratch (no allocations allowed) ----------------
__device__ float g_t[N_NODES * HID];        // transformed features (pre-aggregation)
__device__ float g_h[N_NODES * HID];        // layer activations
__device__ float g_outnorm[N_NODES];
__device__ float g_innorm[N_NODES];
__device__ int   g_degout[N_NODES];
__device__ int   g_degin[N_NODES];
__device__ int   g_rowptr[N_NODES + 1];
__device__ int   g_cursor[N_NODES];
__device__ int   g_col[N_EDGES];            // CSR by dst: src node per edge slot

// ---------------- graph preprocessing ----------------
__global__ void zero_deg_kernel() {
    int i = blockIdx.x * blockDim.x + threadIdx.x;
    if (i < N_NODES) { g_degout[i] = 0; g_degin[i] = 0; }
}

__global__ void hist_kernel(const int* __restrict__ src, const int* __restrict__ dst) {
    int e = blockIdx.x * blockDim.x + threadIdx.x;
    if (e < N_EDGES) {
        atomicAdd(&g_degout[src[e]], 1);
        atomicAdd(&g_degin[dst[e]], 1);
    }
}

__global__ void norm_kernel() {
    int n = blockIdx.x * blockDim.x + threadIdx.x;
    if (n < N_NODES) {
        g_outnorm[n] = rsqrtf(fmaxf((float)g_degout[n], 1.0f));
        g_innorm[n]  = rsqrtf(fmaxf((float)g_degin[n], 1.0f));
    }
}

// Single-block exclusive scan over g_degin -> g_rowptr, g_cursor
__global__ void scan_kernel() {
    __shared__ int sh[1024];
    const int tid = threadIdx.x;
    const int chunk = (N_NODES + 1023) / 1024;   // 49
    const int base = tid * chunk;
    int s = 0;
    for (int i = 0; i < chunk; ++i) {
        int idx = base + i;
        if (idx < N_NODES) s += g_degin[idx];
    }
    sh[tid] = s;
    __syncthreads();
    for (int off = 1; off < 1024; off <<= 1) {
        int v = 0;
        if (tid >= off) v = sh[tid - off];
        __syncthreads();
        if (tid >= off) sh[tid] += v;
        __syncthreads();
    }
    int run = (tid == 0) ? 0 : sh[tid - 1];
    for (int i = 0; i < chunk; ++i) {
        int idx = base + i;
        if (idx < N_NODES) {
            g_rowptr[idx] = run;
            g_cursor[idx] = run;
            run += g_degin[idx];
        }
    }
    if (tid == 1023) g_rowptr[N_NODES] = sh[1023];
}

__global__ void fill_kernel(const int* __restrict__ src, const int* __restrict__ dst) {
    int e = blockIdx.x * blockDim.x + threadIdx.x;
    if (e < N_EDGES) {
        int d = dst[e];
        int p = atomicAdd(&g_cursor[d], 1);
        g_col[p] = src[e];
    }
}

// ---------------- dense transform: g_t = (H @ W) * out_norm ----------------
// block = (32, 8); 8 rows per block; each thread computes cols lane and lane+32
template <int K, bool H_FROM_G>
__global__ void gemm_kernel(const float* __restrict__ Hext, const float* __restrict__ W) {
    __shared__ float Ws[K * 64];
    const int lane = threadIdx.x;
    const int tid = threadIdx.y * 32 + threadIdx.x;
    for (int i = tid; i < K * 64; i += 256) Ws[i] = W[i];
    __syncthreads();

    const int row = blockIdx.x * 8 + threadIdx.y;   // 50000 = 6250 * 8, exact
    const float* H = H_FROM_G ? g_h : Hext;
    const float* hrow = H + (size_t)row * K;

    float acc0 = 0.f, acc1 = 0.f;
#pragma unroll
    for (int k = 0; k < K; k += 4) {
        float4 hv = *reinterpret_cast<const float4*>(hrow + k);
        acc0 += hv.x * Ws[(k + 0) * 64 + lane];
        acc1 += hv.x * Ws[(k + 0) * 64 + lane + 32];
        acc0 += hv.y * Ws[(k + 1) * 64 + lane];
        acc1 += hv.y * Ws[(k + 1) * 64 + lane + 32];
        acc0 += hv.z * Ws[(k + 2) * 64 + lane];
        acc1 += hv.z * Ws[(k + 2) * 64 + lane + 32];
        acc0 += hv.w * Ws[(k + 3) * 64 + lane];
        acc1 += hv.w * Ws[(k + 3) * 64 + lane + 32];
    }
    const float on = g_outnorm[row];
    g_t[(size_t)row * 64 + lane]      = acc0 * on;
    g_t[(size_t)row * 64 + lane + 32] = acc1 * on;
}

// ---------------- aggregation: out[n] = epi( sum_{e in in(n)} t[src_e] ) ----------------
// warp per node, lane owns 2 columns (float2)
template <bool RELU, bool TO_G>
__global__ void agg_kernel(float* __restrict__ outext, const float* __restrict__ bias) {
    const int node = (blockIdx.x * blockDim.x + threadIdx.x) >> 5;
    const int lane = threadIdx.x & 31;
    if (node >= N_NODES) return;

    const int beg = g_rowptr[node];
    const int end = g_rowptr[node + 1];

    float2 a0 = make_float2(0.f, 0.f);
    float2 a1 = make_float2(0.f, 0.f);
    int e = beg;
    for (; e + 1 < end; e += 2) {
        int s0 = __ldg(&g_col[e]);
        int s1 = __ldg(&g_col[e + 1]);
        float2 v0 = *reinterpret_cast<const float2*>(g_t + (size_t)s0 * 64 + lane * 2);
        float2 v1 = *reinterpret_cast<const float2*>(g_t + (size_t)s1 * 64 + lane * 2);
        a0.x += v0.x; a0.y += v0.y;
        a1.x += v1.x; a1.y += v1.y;
    }
    if (e < end) {
        int s0 = __ldg(&g_col[e]);
        float2 v0 = *reinterpret_cast<const float2*>(g_t + (size_t)s0 * 64 + lane * 2);
        a0.x += v0.x; a0.y += v0.y;
    }

    const float inn = g_innorm[node];
    const float2 bv = *reinterpret_cast<const float2*>(bias + lane * 2);
    float ox = (a0.x + a1.x) * inn + bv.x;
    float oy = (a0.y + a1.y) * inn + bv.y;
    if (RELU) { ox = fmaxf(ox, 0.f); oy = fmaxf(oy, 0.f); }

    float* out = TO_G ? g_h : outext;
    *reinterpret_cast<float2*>(out + (size_t)node * 64 + lane * 2) = make_float2(ox, oy);
}

// ---------------- launch ----------------
extern "C" void kernel_launch(void* const* d_in, const int* in_sizes, int n_in,
                              void* d_out, int out_size) {
    const float* features = (const float*)d_in[0];
    const float* W0 = (const float*)d_in[1];
    const float* b0 = (const float*)d_in[2];
    const float* W1 = (const float*)d_in[3];
    const float* b1 = (const float*)d_in[4];
    const float* W2 = (const float*)d_in[5];
    const float* b2 = (const float*)d_in[6];
    const int* src = (const int*)d_in[7];
    const int* dst = (const int*)d_in[8];
    float* out = (float*)d_out;

    const int nodeBlocks = (N_NODES + 255) / 256;   // 196
    const int edgeBlocks = (N_EDGES + 255) / 256;   // 6250
    const dim3 gemmBlock(32, 8);
    const int gemmGrid = N_NODES / 8;               // 6250
    const int aggGrid = (N_NODES * 32 + 255) / 256; // 6250

    // graph preprocessing (recomputed every call; graph-capture safe)
    zero_deg_kernel<<<nodeBlocks, 256>>>();
    hist_kernel<<<edgeBlocks, 256>>>(src, dst);
    norm_kernel<<<nodeBlocks, 256>>>();
    scan_kernel<<<1, 1024>>>();
    fill_kernel<<<edgeBlocks, 256>>>(src, dst);

    // layer 0: 128 -> 64, relu
    gemm_kernel<IN_FEATS, false><<<gemmGrid, gemmBlock>>>(features, W0);
    agg_kernel<true, true><<<aggGrid, 256>>>(nullptr, b0);

    // layer 1: 64 -> 64, relu
    gemm_kernel<HID, true><<<gemmGrid, gemmBlock>>>(nullptr, W1);
    agg_kernel<true, true><<<aggGrid, 256>>>(nullptr, b1);

    // layer 2: 64 -> 64, no activation, write logits
    gemm_kernel<HID, true><<<gemmGrid, gemmBlock>>>(nullptr, W2);
    agg_kernel<false, false><<<aggGrid, 256>>>(out, b2);
}

// round 4
// speedup vs baseline: 1.0012x; 1.0012x over previous
#include <cuda_runtime.h>
#include <cuda_bf16.h>

#define N_NODES  50000
#define N_EDGES  1600000
#define IN_FEATS 128
#define HID      64

// ---------------- device scratch (no allocations allowed) ----------------
__device__ float g_t[N_NODES * HID];        // transformed features (pre-aggregation)
__device__ float g_h[N_NODES * HID];        // layer activations
__device__ float g_outnorm[N_NODES];
__device__ float g_innorm[N_NODES];
__device__ int   g_degout[N_NODES];
__device__ int   g_degin[N_NODES];
__device__ int   g_rowptr[N_NODES + 1];
__device__ int   g_cursor[N_NODES];
__device__ int   g_col[N_EDGES];            // CSR by dst: src node per edge slot

// ---------------- graph preprocessing ----------------
__global__ void zero_deg_kernel() {
    int i = blockIdx.x * blockDim.x + threadIdx.x;
    if (i < N_NODES) { g_degout[i] = 0; g_degin[i] = 0; }
}

__global__ void hist_kernel(const int* __restrict__ src, const int* __restrict__ dst) {
    int e = blockIdx.x * blockDim.x + threadIdx.x;
    if (e < N_EDGES) {
        atomicAdd(&g_degout[src[e]], 1);
        atomicAdd(&g_degin[dst[e]], 1);
    }
}

__global__ void norm_kernel() {
    int n = blockIdx.x * blockDim.x + threadIdx.x;
    if (n < N_NODES) {
        g_outnorm[n] = rsqrtf(fmaxf((float)g_degout[n], 1.0f));
        g_innorm[n]  = rsqrtf(fmaxf((float)g_degin[n], 1.0f));
    }
}

// Single-block exclusive scan over g_degin -> g_rowptr, g_cursor
__global__ void scan_kernel() {
    __shared__ int sh[1024];
    const int tid = threadIdx.x;
    const int chunk = (N_NODES + 1023) / 1024;   // 49
    const int base = tid * chunk;
    int s = 0;
    for (int i = 0; i < chunk; ++i) {
        int idx = base + i;
        if (idx < N_NODES) s += g_degin[idx];
    }
    sh[tid] = s;
    __syncthreads();
    for (int off = 1; off < 1024; off <<= 1) {
        int v = 0;
        if (tid >= off) v = sh[tid - off];
        __syncthreads();
        if (tid >= off) sh[tid] += v;
        __syncthreads();
    }
    int run = (tid == 0) ? 0 : sh[tid - 1];
    for (int i = 0; i < chunk; ++i) {
        int idx = base + i;
        if (idx < N_NODES) {
            g_rowptr[idx] = run;
            g_cursor[idx] = run;
            run += g_degin[idx];
        }
    }
    if (tid == 1023) g_rowptr[N_NODES] = sh[1023];
}

__global__ void fill_kernel(const int* __restrict__ src, const int* __restrict__ dst) {
    int e = blockIdx.x * blockDim.x + threadIdx.x;
    if (e < N_EDGES) {
        int d = dst[e];
        int p = atomicAdd(&g_cursor[d], 1);
        g_col[p] = src[e];
    }
}

// ---------------- dense transform: g_t = (H @ W) * out_norm ----------------
// block = (32, 8); 8 rows per block; each thread computes cols lane and lane+32
template <int K, bool H_FROM_G>
__global__ void gemm_kernel(const float* __restrict__ Hext, const float* __restrict__ W) {
    __shared__ float Ws[K * 64];
    const int lane = threadIdx.x;
    const int tid = threadIdx.y * 32 + threadIdx.x;
    for (int i = tid; i < K * 64; i += 256) Ws[i] = W[i];
    __syncthreads();

    const int row = blockIdx.x * 8 + threadIdx.y;   // 50000 = 6250 * 8, exact
    const float* H = H_FROM_G ? g_h : Hext;
    const float* hrow = H + (size_t)row * K;

    float acc0 = 0.f, acc1 = 0.f;
#pragma unroll
    for (int k = 0; k < K; k += 4) {
        float4 hv = *reinterpret_cast<const float4*>(hrow + k);
        acc0 += hv.x * Ws[(k + 0) * 64 + lane];
        acc1 += hv.x * Ws[(k + 0) * 64 + lane + 32];
        acc0 += hv.y * Ws[(k + 1) * 64 + lane];
        acc1 += hv.y * Ws[(k + 1) * 64 + lane + 32];
        acc0 += hv.z * Ws[(k + 2) * 64 + lane];
        acc1 += hv.z * Ws[(k + 2) * 64 + lane + 32];
        acc0 += hv.w * Ws[(k + 3) * 64 + lane];
        acc1 += hv.w * Ws[(k + 3) * 64 + lane + 32];
    }
    const float on = g_outnorm[row];
    g_t[(size_t)row * 64 + lane]      = acc0 * on;
    g_t[(size_t)row * 64 + lane + 32] = acc1 * on;
}

// ---------------- aggregation: out[n] = epi( sum_{e in in(n)} t[src_e] ) ----------------
// warp per node, lane owns 2 columns (float2)
template <bool RELU, bool TO_G>
__global__ void agg_kernel(float* __restrict__ outext, const float* __restrict__ bias) {
    const int node = (blockIdx.x * blockDim.x + threadIdx.x) >> 5;
    const int lane = threadIdx.x & 31;
    if (node >= N_NODES) return;

    const int beg = g_rowptr[node];
    const int end = g_rowptr[node + 1];

    float2 a0 = make_float2(0.f, 0.f);
    float2 a1 = make_float2(0.f, 0.f);
    int e = beg;
    for (; e + 1 < end; e += 2) {
        int s0 = __ldg(&g_col[e]);
        int s1 = __ldg(&g_col[e + 1]);
        float2 v0 = *reinterpret_cast<const float2*>(g_t + (size_t)s0 * 64 + lane * 2);
        float2 v1 = *reinterpret_cast<const float2*>(g_t + (size_t)s1 * 64 + lane * 2);
        a0.x += v0.x; a0.y += v0.y;
        a1.x += v1.x; a1.y += v1.y;
    }
    if (e < end) {
        int s0 = __ldg(&g_col[e]);
        float2 v0 = *reinterpret_cast<const float2*>(g_t + (size_t)s0 * 64 + lane * 2);
        a0.x += v0.x; a0.y += v0.y;
    }

    const float inn = g_innorm[node];
    const float2 bv = *reinterpret_cast<const float2*>(bias + lane * 2);
    float ox = (a0.x + a1.x) * inn + bv.x;
    float oy = (a0.y + a1.y) * inn + bv.y;
    if (RELU) { ox = fmaxf(ox, 0.f); oy = fmaxf(oy, 0.f); }

    float* out = TO_G ? g_h : outext;
    *reinterpret_cast<float2*>(out + (size_t)node * 64 + lane * 2) = make_float2(ox, oy);
}

// ---------------- launch ----------------
extern "C" void kernel_launch(void* const* d_in, const int* in_sizes, int n_in,
                              void* d_out, int out_size) {
    const float* features = (const float*)d_in[0];
    const float* W0 = (const float*)d_in[1];
    const float* b0 = (const float*)d_in[2];
    const float* W1 = (const float*)d_in[3];
    const float* b1 = (const float*)d_in[4];
    const float* W2 = (const float*)d_in[5];
    const float* b2 = (const float*)d_in[6];
    const int* src = (const int*)d_in[7];
    const int* dst = (const int*)d_in[8];
    float* out = (float*)d_out;

    const int nodeBlocks = (N_NODES + 255) / 256;   // 196
    const int edgeBlocks = (N_EDGES + 255) / 256;   // 6250
    const dim3 gemmBlock(32, 8);
    const int gemmGrid = N_NODES / 8;               // 6250
    const int aggGrid = (N_NODES * 32 + 255) / 256; // 6250

    // graph preprocessing (recomputed every call; graph-capture safe)
    zero_deg_kernel<<<nodeBlocks, 256>>>();
    hist_kernel<<<edgeBlocks, 256>>>(src, dst);
    norm_kernel<<<nodeBlocks, 256>>>();
    scan_kernel<<<1, 1024>>>();
    fill_kernel<<<edgeBlocks, 256>>>(src, dst);

    // layer 0: 128 -> 64, relu
    gemm_kernel<IN_FEATS, false><<<gemmGrid, gemmBlock>>>(features, W0);
    agg_kernel<true, true><<<aggGrid, 256>>>(nullptr, b0);

    // layer 1: 64 -> 64, relu
    gemm_kernel<HID, true><<<gemmGrid, gemmBlock>>>(nullptr, W1);
    agg_kernel<true, true><<<aggGrid, 256>>>(nullptr, b1);

    // layer 2: 64 -> 64, no activation, write logits
    gemm_kernel<HID, true><<<gemmGrid, gemmBlock>>>(nullptr, W2);
    agg_kernel<false, false><<<aggGrid, 256>>>(out, b2);
}